// round 10
// baseline (speedup 1.0000x reference)
#include <cuda_runtime.h>
#include <cuda_bf16.h>

// FuzzyLayer: out[b,s,d*I+i] = exp(-(x[b,s,i]-mu[d,i])^2 / sigma[d,i])
// B=16, S=2048, I=256, D=8.  256 MB write + 32 MB read -> HBM-write-bound.
//
// R9 -> R10: cp.async fill lost (47.6) -> revert to R4's LDG->STS fill.
// Exact R4 structure (best, 45.5us); single A/B change: plain write-back
// stores instead of __stcs evict-first. Rationale: 126 MB L2 (half the
// output) can elastically absorb store bursts and drain via writeback
// engines, decoupling warp store-issue from DRAM drain; evict-first forces
// eager eviction. This is the only untested axis on the winner.
// Kept: ROWS=32 tile, grid 1024 short blocks (desync), single cooperative
// SMEM fill + ONE barrier, poly coeffs in regs (exp2((a*x+b)*x+e)), all 8
// 'd' groups co-resident, float4 traffic, __launch_bounds__(512,4).

static constexpr int BS   = 16 * 2048;     // 32768 rows
static constexpr int ROWS = 32;            // rows per block (32 KB smem)

__device__ __forceinline__ float ex2_approx(float t) {
    float r;
    asm("ex2.approx.ftz.f32 %0, %1;" : "=f"(r) : "f"(t));
    return r;
}

__global__ void __launch_bounds__(512, 4)
fuzzy_kernel(const float4* __restrict__ x4,
             const float4* __restrict__ fp4,
             float4* __restrict__ out4)
{
    __shared__ float4 sx[ROWS * 64];         // 32 KB: ROWS rows of x (256 f32)

    const int tid = threadIdx.x;
    const int i4  = tid & 63;                // float4 group within I
    const int d   = tid >> 6;                // fuzzy degree

    // fuzzy_params (2048,2) row-major: fp[2j]=mu_j, fp[2j+1]=sigma_j, j=d*256+i.
    const float4 p0 = fp4[d * 128 + i4 * 2];
    const float4 p1 = fp4[d * 128 + i4 * 2 + 1];

    const float L2E = 1.4426950408889634f;
    // exponent(x) = rs*(x-mu)^2 = (a*x + b)*x + e
    const float a0 = -L2E / p0.y, b0 = -2.f * a0 * p0.x, e0 = a0 * p0.x * p0.x;
    const float a1 = -L2E / p0.w, b1 = -2.f * a1 * p0.z, e1 = a1 * p0.z * p0.z;
    const float a2 = -L2E / p1.y, b2 = -2.f * a2 * p1.x, e2 = a2 * p1.x * p1.x;
    const float a3 = -L2E / p1.w, b3 = -2.f * a3 * p1.z, e3 = a3 * p1.z * p1.z;

    const int bs0 = blockIdx.x * ROWS;

    // Cooperative fill: 2048 float4 / 512 threads = 4 per thread (MLP=4).
    const float4* __restrict__ src = x4 + (size_t)bs0 * 64;
#pragma unroll
    for (int k = 0; k < ROWS * 64 / 512; ++k)
        sx[tid + k * 512] = src[tid + k * 512];
    __syncthreads();

    float4* __restrict__ oout = out4 + (size_t)bs0 * 512 + tid;

#pragma unroll 4
    for (int r = 0; r < ROWS; ++r) {
        const float4 xv = sx[r * 64 + i4];

        float4 o;
        o.x = ex2_approx(fmaf(fmaf(a0, xv.x, b0), xv.x, e0));
        o.y = ex2_approx(fmaf(fmaf(a1, xv.y, b1), xv.y, e1));
        o.z = ex2_approx(fmaf(fmaf(a2, xv.z, b2), xv.z, e2));
        o.w = ex2_approx(fmaf(fmaf(a3, xv.w, b3), xv.w, e3));

        oout[r * 512] = o;                  // plain write-back STG.128
    }
}

extern "C" void kernel_launch(void* const* d_in, const int* in_sizes, int n_in,
                              void* d_out, int out_size)
{
    const float4* x4  = (const float4*)d_in[0];   // x: (16,2048,256) f32
    const float4* fp4 = (const float4*)d_in[1];   // fuzzy_params: (2048,2) f32
    float4* out4      = (float4*)d_out;           // (16,2048,2048) f32

    fuzzy_kernel<<<BS / ROWS, 512>>>(x4, fp4, out4);   // 1024 blocks
}